// round 8
// baseline (speedup 1.0000x reference)
#include <cuda_runtime.h>
#include <cuda_fp16.h>
#include <math.h>
#include <stdint.h>

#define N_E    8192
#define E_DIM  32
#define T_TOK  32768
#define KH     32
#define ROW_B  80             // smem row stride bytes (conflict-free, 16B aligned)
#define ROW_W  20
#define NCHUNK 256
#define CHUNKS 32
#define MCTA   128
#define GRID_MAIN 256
#define WINDOW 1.2e-2f
#define CAND_CAP 16

// ---- device scratch ----
__device__ float  g_en  [N_E * E_DIM];   // normalized codebook fp32 (rescore/gather)
__device__ float  g_bias[N_E];           // -0.5 * ||en||^2 (stage-B only)
__device__ __half g_Bp  [N_E * KH];      // fp16 codebook rows
__device__ float  g_part[GRID_MAIN];

// ---- smem layout (bytes) ----
#define A_OFF    0
#define B0_OFF   10240
#define B1_OFF   30720
#define SMEM_TOTAL 51456

#define CP_ASYNC16(s, g) asm volatile("cp.async.cg.shared.global [%0], [%1], 16;" :: "r"(s), "l"(g) : "memory")
#define CP_COMMIT()      asm volatile("cp.async.commit_group;" ::: "memory")
#define CP_WAIT1()       asm volatile("cp.async.wait_group 1;" ::: "memory")
#define CP_WAIT0()       asm volatile("cp.async.wait_group 0;" ::: "memory")

// NON-trans: B tile is [n][k] row-major; direct ldmatrix gives the
// {n = lane>>2, k = 2*(lane&3)} B fragment (same mapping the round-6 LDS
// version used). .trans was the round-7 bug.
#define LDSM_X4(r0, r1, r2, r3, a)                                              \
    asm volatile("ldmatrix.sync.aligned.m8n8.x4.shared.b16 "                    \
                 "{%0,%1,%2,%3}, [%4];"                                         \
                 : "=r"(r0), "=r"(r1), "=r"(r2), "=r"(r3) : "r"(a))

__device__ __forceinline__ uint32_t smem_u32(const void* p) {
    uint32_t a;
    asm("{ .reg .u64 t; cvta.to.shared.u64 t, %1; cvt.u32.u64 %0, t; }" : "=r"(a) : "l"(p));
    return a;
}

// fp16-accumulator HMMA: c0 = (token row g, codes 2tig..+1), c1 = (row g+8)
__device__ __forceinline__ void mma_h(uint32_t& c0, uint32_t& c1,
                                      uint32_t a0, uint32_t a1, uint32_t a2, uint32_t a3,
                                      uint32_t b0, uint32_t b1) {
    asm volatile("mma.sync.aligned.m16n8k16.row.col.f16.f16.f16.f16 "
                 "{%0,%1}, {%2,%3,%4,%5}, {%6,%7}, {%0,%1};"
                 : "+r"(c0), "+r"(c1)
                 : "r"(a0), "r"(a1), "r"(a2), "r"(a3), "r"(b0), "r"(b1));
}

// rare-path top-4 insertion
#define INS4(s, n, b1, i1, b2, i2, b3, i3, b4, i4)                             \
    do { float _s = (s); int _n = (n);                                         \
         if (_s > (b4)) {                                                      \
             if (_s > (b2)) {                                                  \
                 if (_s > (b1)) { (b4)=(b3);(i4)=(i3); (b3)=(b2);(i3)=(i2);    \
                                  (b2)=(b1);(i2)=(i1); (b1)=_s;(i1)=_n; }      \
                 else { (b4)=(b3);(i4)=(i3); (b3)=(b2);(i3)=(i2); (b2)=_s;(i2)=_n; } \
             } else {                                                          \
                 if (_s > (b3)) { (b4)=(b3);(i4)=(i3); (b3)=_s;(i3)=_n; }      \
                 else { (b4)=_s;(i4)=_n; }                                     \
             }                                                                 \
         } } while (0)

// =====================================================================
// Prep: normalize codebook -> g_en (fp32), g_bias, fp16 rows g_Bp
// =====================================================================
__global__ void prep_kernel(const float* __restrict__ emb) {
    int row  = blockIdx.x * 8 + (threadIdx.x >> 5);
    int lane = threadIdx.x & 31;
    float v  = emb[row * E_DIM + lane];
    float ss = v * v;
    #pragma unroll
    for (int o = 16; o; o >>= 1) ss += __shfl_xor_sync(0xFFFFFFFFu, ss, o);
    float inv = 1.0f / fmaxf(sqrtf(ss), 1e-12f);
    float e = v * inv;
    g_en[row * E_DIM + lane] = e;
    float s2 = e * e;
    #pragma unroll
    for (int o = 16; o; o >>= 1) s2 += __shfl_xor_sync(0xFFFFFFFFu, s2, o);
    if (lane == 0) g_bias[row] = -0.5f * s2;
    g_Bp[(size_t)row * KH + lane] = __float2half_rn(e);
}

// =====================================================================
// Main: K=32 fp16-acc HMMA + ldmatrix B + top-4 window, fp32 rescore
// =====================================================================
__device__ __forceinline__ void prefetch_chunk(int ch, uint32_t bbase, int tid) {
    const char* src = (const char*)(g_Bp + (size_t)(ch * NCHUNK + tid) * KH);
    uint32_t dst = bbase + tid * ROW_B;
    #pragma unroll
    for (int i = 0; i < 4; i++)
        CP_ASYNC16(dst + i * 16, src + i * 16);
}

__global__ void __launch_bounds__(256, 2) vq_main_kernel(const float* __restrict__ z,
                                                         float* __restrict__ out) {
    extern __shared__ char smem[];
    const uint32_t sb = smem_u32(smem);
    const int tid  = threadIdx.x;
    const int lane = tid & 31;
    const int w    = tid >> 5;
    const int tok0 = blockIdx.x * MCTA;
    const int g    = lane >> 2;
    const int tig  = lane & 3;

    prefetch_chunk(0, sb + B0_OFF, tid); CP_COMMIT();
    prefetch_chunk(1, sb + B1_OFF, tid); CP_COMMIT();

    // build A tile (threads 0-127): one token per thread, plain fp16
    if (tid < 128) {
        const int t = tok0 + tid;
        float x[E_DIM];
        const float4* zr = (const float4*)(z + (size_t)t * E_DIM);
        float ss = 0.0f;
        #pragma unroll
        for (int j = 0; j < 8; j++) {
            float4 v = zr[j];
            x[4*j+0] = v.x; x[4*j+1] = v.y; x[4*j+2] = v.z; x[4*j+3] = v.w;
            ss += v.x*v.x + v.y*v.y + v.z*v.z + v.w*v.w;
        }
        float inv = 1.0f / fmaxf(sqrtf(ss), 1e-12f);
        __half* arow = (__half*)(smem + A_OFF + tid * ROW_B);
        #pragma unroll
        for (int d = 0; d < E_DIM; d++)
            arow[d] = __float2half_rn(x[d] * inv);
    }
    __syncthreads();

    // A fragments: 2 ksteps x 4 regs (layout validated rounds 4-6)
    uint32_t af[2][4];
    {
        const uint32_t* aw = (const uint32_t*)(smem + A_OFF);
        const int r0 = w * 16 + g;
        #pragma unroll
        for (int ks = 0; ks < 2; ks++) {
            int base = ks * 8 + tig;
            af[ks][0] = aw[r0 * ROW_W + base];
            af[ks][1] = aw[(r0 + 8) * ROW_W + base];
            af[ks][2] = aw[r0 * ROW_W + base + 4];
            af[ks][3] = aw[(r0 + 8) * ROW_W + base + 4];
        }
    }

    float b1A = -3.4e38f, b2A = -3.4e38f, b3A = -3.4e38f, b4A = -3.4e38f;
    float b1B = -3.4e38f, b2B = -3.4e38f, b3B = -3.4e38f, b4B = -3.4e38f;
    int   i1A = 0, i2A = 0, i3A = 0, i4A = 0;
    int   i1B = 0, i2B = 0, i3B = 0, i4B = 0;
    __half b4hA = __float2half_rd(-60000.0f);
    __half b4hB = __float2half_rd(-60000.0f);

    // ldmatrix lane->address: lanes 8i..8i+7 supply the 8 row addrs of matrix i.
    // matrix 0/1 = codes r0..r0+7, k-halves 0-7 / 8-15; matrices 2/3 = k 16-31.
    const uint32_t lmo = (uint32_t)(lane & 7) * ROW_B + (uint32_t)(lane >> 3) * 16;

    for (int ch = 0; ch < CHUNKS; ch++) {
        CP_WAIT1();
        __syncthreads();
        const uint32_t bbase = sb + ((ch & 1) ? B1_OFF : B0_OFF);
        const int nbase = ch * NCHUNK;

        #pragma unroll 4
        for (int np = 0; np < 16; np++) {            // 16 codes per iteration
            uint32_t q0, q1, q2, q3, r0, r1, r2, r3;
            uint32_t a0 = bbase + (uint32_t)np * (16 * ROW_B) + lmo;
            LDSM_X4(q0, q1, q2, q3, a0);             // codes n0..n0+7,  K=32
            LDSM_X4(r0, r1, r2, r3, a0 + 8 * ROW_B); // codes n0+8..+15, K=32
            uint32_t c00 = 0u, c01 = 0u, c10 = 0u, c11 = 0u;
            mma_h(c00, c01, af[0][0], af[0][1], af[0][2], af[0][3], q0, q1);
            mma_h(c00, c01, af[1][0], af[1][1], af[1][2], af[1][3], q2, q3);
            mma_h(c10, c11, af[0][0], af[0][1], af[0][2], af[0][3], r0, r1);
            mma_h(c10, c11, af[1][0], af[1][1], af[1][2], af[1][3], r2, r3);

            const int nb0 = nbase + np * 16 + 2 * tig;
            // tokens A (row g): c00 = codes nb0,nb0+1 ; c10 = nb0+8,nb0+9
            {
                __half2 hm = __hmax2(*(__half2*)&c00, *(__half2*)&c10);
                __half  mx = __hmax(__low2half(hm), __high2half(hm));
                if (__hgt(mx, b4hA)) {
                    float2 f0 = __half22float2(*(__half2*)&c00);
                    float2 f1 = __half22float2(*(__half2*)&c10);
                    INS4(f0.x, nb0,     b1A, i1A, b2A, i2A, b3A, i3A, b4A, i4A);
                    INS4(f0.y, nb0 + 1, b1A, i1A, b2A, i2A, b3A, i3A, b4A, i4A);
                    INS4(f1.x, nb0 + 8, b1A, i1A, b2A, i2A, b3A, i3A, b4A, i4A);
                    INS4(f1.y, nb0 + 9, b1A, i1A, b2A, i2A, b3A, i3A, b4A, i4A);
                    b4hA = __float2half_rd(fmaxf(b4A, -60000.0f));
                }
            }
            // tokens B (row g+8): c01, c11
            {
                __half2 hm = __hmax2(*(__half2*)&c01, *(__half2*)&c11);
                __half  mx = __hmax(__low2half(hm), __high2half(hm));
                if (__hgt(mx, b4hB)) {
                    float2 f0 = __half22float2(*(__half2*)&c01);
                    float2 f1 = __half22float2(*(__half2*)&c11);
                    INS4(f0.x, nb0,     b1B, i1B, b2B, i2B, b3B, i3B, b4B, i4B);
                    INS4(f0.y, nb0 + 1, b1B, i1B, b2B, i2B, b3B, i3B, b4B, i4B);
                    INS4(f1.x, nb0 + 8, b1B, i1B, b2B, i2B, b3B, i3B, b4B, i4B);
                    INS4(f1.y, nb0 + 9, b1B, i1B, b2B, i2B, b3B, i3B, b4B, i4B);
                    b4hB = __float2half_rd(fmaxf(b4B, -60000.0f));
                }
            }
        }
        __syncthreads();
        if (ch + 2 < CHUNKS) prefetch_chunk(ch + 2, bbase, tid);
        CP_COMMIT();
    }
    CP_WAIT0();
    __syncthreads();

    // ---- candidate collection (reuse B0 region) ----
    int* s_cnt  = (int*)(smem + B0_OFF);
    int* s_list = (int*)(smem + B0_OFF + 512);
    if (tid < 128) s_cnt[tid] = 0;
    __syncthreads();

    float mA = b1A, mB = b1B;
    #pragma unroll
    for (int o = 1; o <= 2; o <<= 1) {
        mA = fmaxf(mA, __shfl_xor_sync(0xFFFFFFFFu, mA, o));
        mB = fmaxf(mB, __shfl_xor_sync(0xFFFFFFFFu, mB, o));
    }
    const int tokA = w * 16 + g;
    const int tokB = tokA + 8;
    float thrA = mA - WINDOW, thrB = mB - WINDOW;
    if (b1A >= thrA) { int p = atomicAdd(&s_cnt[tokA], 1); if (p < CAND_CAP) s_list[tokA * CAND_CAP + p] = i1A; }
    if (b2A >= thrA) { int p = atomicAdd(&s_cnt[tokA], 1); if (p < CAND_CAP) s_list[tokA * CAND_CAP + p] = i2A; }
    if (b3A >= thrA) { int p = atomicAdd(&s_cnt[tokA], 1); if (p < CAND_CAP) s_list[tokA * CAND_CAP + p] = i3A; }
    if (b4A >= thrA) { int p = atomicAdd(&s_cnt[tokA], 1); if (p < CAND_CAP) s_list[tokA * CAND_CAP + p] = i4A; }
    if (b1B >= thrB) { int p = atomicAdd(&s_cnt[tokB], 1); if (p < CAND_CAP) s_list[tokB * CAND_CAP + p] = i1B; }
    if (b2B >= thrB) { int p = atomicAdd(&s_cnt[tokB], 1); if (p < CAND_CAP) s_list[tokB * CAND_CAP + p] = i2B; }
    if (b3B >= thrB) { int p = atomicAdd(&s_cnt[tokB], 1); if (p < CAND_CAP) s_list[tokB * CAND_CAP + p] = i3B; }
    if (b4B >= thrB) { int p = atomicAdd(&s_cnt[tokB], 1); if (p < CAND_CAP) s_list[tokB * CAND_CAP + p] = i4B; }
    __syncthreads();

    // ---- stage B: fp32 rescore + outputs + loss ----
    float lsum = 0.0f;
    if (tid < 128) {
        const int t = tok0 + tid;
        float zn[E_DIM];
        const float4* zr = (const float4*)(z + (size_t)t * E_DIM);
        float ss = 0.0f;
        #pragma unroll
        for (int j = 0; j < 8; j++) {
            float4 v = zr[j];
            zn[4*j+0] = v.x; zn[4*j+1] = v.y; zn[4*j+2] = v.z; zn[4*j+3] = v.w;
            ss += v.x*v.x + v.y*v.y + v.z*v.z + v.w*v.w;
        }
        float inv = 1.0f / fmaxf(sqrtf(ss), 1e-12f);
        #pragma unroll
        for (int d = 0; d < E_DIM; d++) zn[d] *= inv;

        int nc = s_cnt[tid]; if (nc > CAND_CAP) nc = CAND_CAP;
        float best = -3.4e38f;
        int   bi   = 0x7FFFFFFF;
        for (int j = 0; j < nc; j++) {
            int ci = s_list[tid * CAND_CAP + j];
            const float* er = g_en + (size_t)ci * E_DIM;
            float dot = 0.0f;
            #pragma unroll
            for (int d = 0; d < E_DIM; d++) dot = fmaf(zn[d], er[d], dot);
            float s = dot + g_bias[ci];
            if (s > best || (s == best && ci < bi)) { best = s; bi = ci; }
        }

        float o[E_DIM];
        const float* eq = g_en + (size_t)bi * E_DIM;
        #pragma unroll
        for (int d = 0; d < E_DIM; d++) {
            float df = eq[d] - zn[d];
            lsum += df * df;
            o[d] = zn[d] + df;
        }
        float4* orow = (float4*)(out + (size_t)t * E_DIM);
        #pragma unroll
        for (int j = 0; j < 8; j++)
            orow[j] = make_float4(o[4*j], o[4*j+1], o[4*j+2], o[4*j+3]);
        out[(size_t)T_TOK * E_DIM + 1 + t] = (float)bi;
    }

    __syncthreads();
    float* s_red = (float*)smem;
    s_red[tid] = lsum;
    __syncthreads();
    #pragma unroll
    for (int k = 128; k; k >>= 1) {
        if (tid < k) s_red[tid] += s_red[tid + k];
        __syncthreads();
    }
    if (tid == 0) g_part[blockIdx.x] = s_red[0];
}

// =====================================================================
// Final loss: 1.25 * sum / (T*D)
// =====================================================================
__global__ void finish_kernel(float* __restrict__ out) {
    __shared__ float s[256];
    int tid = threadIdx.x;
    s[tid] = g_part[tid];
    __syncthreads();
    #pragma unroll
    for (int k = 128; k; k >>= 1) {
        if (tid < k) s[tid] += s[tid + k];
        __syncthreads();
    }
    if (tid == 0) out[(size_t)T_TOK * E_DIM] = 1.25f * s[0] / (float)(T_TOK * E_DIM);
}

extern "C" void kernel_launch(void* const* d_in, const int* in_sizes, int n_in,
                              void* d_out, int out_size) {
    const float* z   = (const float*)d_in[0];
    const float* emb = (const float*)d_in[1];
    float* out = (float*)d_out;

    cudaFuncSetAttribute(vq_main_kernel, cudaFuncAttributeMaxDynamicSharedMemorySize, SMEM_TOTAL);

    prep_kernel<<<N_E / 8, 256>>>(emb);
    vq_main_kernel<<<GRID_MAIN, 256, SMEM_TOTAL>>>(z, out);
    finish_kernel<<<1, 256>>>(out);
}

// round 10
// speedup vs baseline: 1.2137x; 1.2137x over previous
#include <cuda_runtime.h>
#include <math.h>
#include <stdint.h>

#define N_E    8192
#define E_DIM  32
#define T_TOK  32768
#define ROW_B  48             // int8 row stride: 32B data + pad (conflict-free, 16B aligned)
#define NCHUNK 256
#define CHUNKS 32
#define MCTA   64
#define GRID_MAIN 512
#define WINDOW_I 800          // ~0.05 in float units (127^2 scale); ~11 sigma of int-noise
#define CAND_CAP 16
#define NEG_I  (-2147483647-1)

// ---- device scratch ----
__device__ float  g_en  [N_E * E_DIM];   // normalized codebook fp32 (rescore/gather)
__device__ float  g_bias[N_E];           // -0.5 * ||en||^2 (stage-B only)
__device__ char   g_Bq  [N_E * 32];      // int8 codebook rows (rn(127*e))
__device__ float  g_part[GRID_MAIN];

// ---- smem layout (bytes) ----
#define A_OFF    0
#define B0_OFF   3072
#define B1_OFF   15360
#define SMEM_TOTAL 27648
// after mainloop, B0 is reused: cnt[64] ints @B0, list[64][16] ints @B0+256

#define CP_ASYNC16(s, g) asm volatile("cp.async.cg.shared.global [%0], [%1], 16;" :: "r"(s), "l"(g) : "memory")
#define CP_COMMIT()      asm volatile("cp.async.commit_group;" ::: "memory")
#define CP_WAIT1()       asm volatile("cp.async.wait_group 1;" ::: "memory")
#define CP_WAIT0()       asm volatile("cp.async.wait_group 0;" ::: "memory")

// non-trans ldmatrix: 4 8x16B matrices; lanes 8i..8i+7 give row addrs of matrix i
#define LDSM_X4(r0, r1, r2, r3, a)                                              \
    asm volatile("ldmatrix.sync.aligned.m8n8.x4.shared.b16 "                    \
                 "{%0,%1,%2,%3}, [%4];"                                         \
                 : "=r"(r0), "=r"(r1), "=r"(r2), "=r"(r3) : "r"(a))

__device__ __forceinline__ uint32_t smem_u32(const void* p) {
    uint32_t a;
    asm("{ .reg .u64 t; cvta.to.shared.u64 t, %1; cvt.u32.u64 %0, t; }" : "=r"(a) : "l"(p));
    return a;
}

// s8 IMMA m16n8k32: c0=(row g, col 2tig) c1=(g,2tig+1) c2=(g+8,2tig) c3=(g+8,2tig+1)
__device__ __forceinline__ void imma(int& c0, int& c1, int& c2, int& c3,
                                     uint32_t a0, uint32_t a1, uint32_t a2, uint32_t a3,
                                     uint32_t b0, uint32_t b1) {
    asm volatile("mma.sync.aligned.m16n8k32.row.col.s32.s8.s8.s32 "
                 "{%0,%1,%2,%3}, {%4,%5,%6,%7}, {%8,%9}, {%0,%1,%2,%3};"
                 : "+r"(c0), "+r"(c1), "+r"(c2), "+r"(c3)
                 : "r"(a0), "r"(a1), "r"(a2), "r"(a3), "r"(b0), "r"(b1));
}

// rare-path int top-4 insertion
#define INS4(s, n, b1, i1, b2, i2, b3, i3, b4, i4)                             \
    do { int _s = (s); int _n = (n);                                           \
         if (_s > (b4)) {                                                      \
             if (_s > (b2)) {                                                  \
                 if (_s > (b1)) { (b4)=(b3);(i4)=(i3); (b3)=(b2);(i3)=(i2);    \
                                  (b2)=(b1);(i2)=(i1); (b1)=_s;(i1)=_n; }      \
                 else { (b4)=(b3);(i4)=(i3); (b3)=(b2);(i3)=(i2); (b2)=_s;(i2)=_n; } \
             } else {                                                          \
                 if (_s > (b3)) { (b4)=(b3);(i4)=(i3); (b3)=_s;(i3)=_n; }      \
                 else { (b4)=_s;(i4)=_n; }                                     \
             }                                                                 \
         } } while (0)

// =====================================================================
// Prep: normalize codebook -> g_en (fp32), g_bias, int8 rows g_Bq
// =====================================================================
__global__ void prep_kernel(const float* __restrict__ emb) {
    int row  = blockIdx.x * 8 + (threadIdx.x >> 5);
    int lane = threadIdx.x & 31;
    float v  = emb[row * E_DIM + lane];
    float ss = v * v;
    #pragma unroll
    for (int o = 16; o; o >>= 1) ss += __shfl_xor_sync(0xFFFFFFFFu, ss, o);
    float inv = 1.0f / fmaxf(sqrtf(ss), 1e-12f);
    float e = v * inv;
    g_en[row * E_DIM + lane] = e;
    float s2 = e * e;
    #pragma unroll
    for (int o = 16; o; o >>= 1) s2 += __shfl_xor_sync(0xFFFFFFFFu, s2, o);
    if (lane == 0) g_bias[row] = -0.5f * s2;
    g_Bq[row * 32 + lane] = (char)__float2int_rn(e * 127.0f);
}

// =====================================================================
// Main: int8 IMMA coarse (K=32, 1 LDSM + 2 IMMA per 16 codes) +
// top-4 window candidates; stage-B fp32 rescore + outputs + loss
// =====================================================================
__device__ __forceinline__ void prefetch_chunk(int ch, uint32_t bbase, int tid) {
    // 256 code rows, 128 threads: rows tid and tid+128, 2x16B each
    #pragma unroll
    for (int h = 0; h < 2; h++) {
        int row = tid + h * 128;
        const char* src = g_Bq + (size_t)(ch * NCHUNK + row) * 32;
        uint32_t dst = bbase + row * ROW_B;
        CP_ASYNC16(dst,      src);
        CP_ASYNC16(dst + 16, src + 16);
    }
}

__global__ void __launch_bounds__(128, 4) vq_main_kernel(const float* __restrict__ z,
                                                         float* __restrict__ out) {
    extern __shared__ char smem[];
    const uint32_t sb = smem_u32(smem);
    const int tid  = threadIdx.x;
    const int lane = tid & 31;
    const int w    = tid >> 5;          // 4 warps, warp = 16 token rows
    const int tok0 = blockIdx.x * MCTA;
    const int g    = lane >> 2;
    const int tig  = lane & 3;

    prefetch_chunk(0, sb + B0_OFF, tid); CP_COMMIT();
    prefetch_chunk(1, sb + B1_OFF, tid); CP_COMMIT();

    // build int8 A tile (threads 0-63): one token per thread
    if (tid < MCTA) {
        const int t = tok0 + tid;
        float x[E_DIM];
        const float4* zr = (const float4*)(z + (size_t)t * E_DIM);
        float ss = 0.0f;
        #pragma unroll
        for (int j = 0; j < 8; j++) {
            float4 v = zr[j];
            x[4*j+0] = v.x; x[4*j+1] = v.y; x[4*j+2] = v.z; x[4*j+3] = v.w;
            ss += v.x*v.x + v.y*v.y + v.z*v.z + v.w*v.w;
        }
        float inv = 1.0f / fmaxf(sqrtf(ss), 1e-12f);
        char* arow = smem + A_OFF + tid * ROW_B;
        #pragma unroll
        for (int d = 0; d < E_DIM; d++)
            arow[d] = (char)__float2int_rn(x[d] * inv * 127.0f);
    }
    __syncthreads();

    // A fragments (4 regs): rows w*16+g / +8, bytes 4tig / 16+4tig
    // (matches s8 m16n8k32 A frag: thread holds k = 4*tig..+3 and +16)
    uint32_t af0, af1, af2, af3;
    {
        const char* ab = smem + A_OFF;
        const int r0 = w * 16 + g;
        af0 = *(const uint32_t*)(ab + r0 * ROW_B + 4 * tig);
        af1 = *(const uint32_t*)(ab + (r0 + 8) * ROW_B + 4 * tig);
        af2 = *(const uint32_t*)(ab + r0 * ROW_B + 16 + 4 * tig);
        af3 = *(const uint32_t*)(ab + (r0 + 8) * ROW_B + 16 + 4 * tig);
    }

    int b1A = NEG_I, b2A = NEG_I, b3A = NEG_I, b4A = NEG_I;
    int b1B = NEG_I, b2B = NEG_I, b3B = NEG_I, b4B = NEG_I;
    int i1A = 0, i2A = 0, i3A = 0, i4A = 0;
    int i1B = 0, i2B = 0, i3B = 0, i4B = 0;

    // FIXED ldmatrix address map:
    //   m0 (lanes 0-7):   codes r..r+7,   k bytes 0-15
    //   m1 (lanes 8-15):  codes r..r+7,   k bytes 16-31
    //   m2 (lanes 16-23): codes r+8..r+15, k bytes 0-15
    //   m3 (lanes 24-31): codes r+8..r+15, k bytes 16-31
    const uint32_t lmo = (uint32_t)(lane & 7) * ROW_B
                       + (uint32_t)((lane >> 3) & 1) * 16
                       + (uint32_t)(lane >> 4) * (8 * ROW_B);

    for (int ch = 0; ch < CHUNKS; ch++) {
        CP_WAIT1();
        __syncthreads();
        const uint32_t bbase = sb + ((ch & 1) ? B1_OFF : B0_OFF);
        const int nbase = ch * NCHUNK;

        #pragma unroll 4
        for (int np = 0; np < 16; np++) {            // 16 codes per iteration
            uint32_t q0, q1, q2, q3;
            LDSM_X4(q0, q1, q2, q3, bbase + (uint32_t)np * (16 * ROW_B) + lmo);
            int c0 = 0, c1 = 0, c2 = 0, c3 = 0;
            int d0 = 0, d1 = 0, d2 = 0, d3 = 0;
            imma(c0, c1, c2, c3, af0, af1, af2, af3, q0, q1);   // codes n0..n0+7
            imma(d0, d1, d2, d3, af0, af1, af2, af3, q2, q3);   // codes n0+8..+15

            const int nb0 = nbase + np * 16 + 2 * tig;
            // token A (row g): c0,c1 -> nb0,nb0+1 ; d0,d1 -> nb0+8,+9
            {
                int m4 = max(max(c0, c1), max(d0, d1));
                if (m4 > b4A) {
                    INS4(c0, nb0,     b1A, i1A, b2A, i2A, b3A, i3A, b4A, i4A);
                    INS4(c1, nb0 + 1, b1A, i1A, b2A, i2A, b3A, i3A, b4A, i4A);
                    INS4(d0, nb0 + 8, b1A, i1A, b2A, i2A, b3A, i3A, b4A, i4A);
                    INS4(d1, nb0 + 9, b1A, i1A, b2A, i2A, b3A, i3A, b4A, i4A);
                }
            }
            // token B (row g+8): c2,c3,d2,d3
            {
                int m4 = max(max(c2, c3), max(d2, d3));
                if (m4 > b4B) {
                    INS4(c2, nb0,     b1B, i1B, b2B, i2B, b3B, i3B, b4B, i4B);
                    INS4(c3, nb0 + 1, b1B, i1B, b2B, i2B, b3B, i3B, b4B, i4B);
                    INS4(d2, nb0 + 8, b1B, i1B, b2B, i2B, b3B, i3B, b4B, i4B);
                    INS4(d3, nb0 + 9, b1B, i1B, b2B, i2B, b3B, i3B, b4B, i4B);
                }
            }
        }
        __syncthreads();
        if (ch + 2 < CHUNKS) prefetch_chunk(ch + 2, bbase, tid);
        CP_COMMIT();
    }
    CP_WAIT0();
    __syncthreads();

    // ---- candidate collection (reuse B0 region) ----
    int* s_cnt  = (int*)(smem + B0_OFF);
    int* s_list = (int*)(smem + B0_OFF + 256);
    if (tid < MCTA) s_cnt[tid] = 0;
    __syncthreads();

    int mA = b1A, mB = b1B;
    #pragma unroll
    for (int o = 1; o <= 2; o <<= 1) {
        mA = max(mA, __shfl_xor_sync(0xFFFFFFFFu, mA, o));
        mB = max(mB, __shfl_xor_sync(0xFFFFFFFFu, mB, o));
    }
    const int tokA = w * 16 + g;
    const int tokB = tokA + 8;
    int thrA = mA - WINDOW_I, thrB = mB - WINDOW_I;
    if (b1A >= thrA) { int p = atomicAdd(&s_cnt[tokA], 1); if (p < CAND_CAP) s_list[tokA * CAND_CAP + p] = i1A; }
    if (b2A >= thrA) { int p = atomicAdd(&s_cnt[tokA], 1); if (p < CAND_CAP) s_list[tokA * CAND_CAP + p] = i2A; }
    if (b3A >= thrA) { int p = atomicAdd(&s_cnt[tokA], 1); if (p < CAND_CAP) s_list[tokA * CAND_CAP + p] = i3A; }
    if (b4A >= thrA) { int p = atomicAdd(&s_cnt[tokA], 1); if (p < CAND_CAP) s_list[tokA * CAND_CAP + p] = i4A; }
    if (b1B >= thrB) { int p = atomicAdd(&s_cnt[tokB], 1); if (p < CAND_CAP) s_list[tokB * CAND_CAP + p] = i1B; }
    if (b2B >= thrB) { int p = atomicAdd(&s_cnt[tokB], 1); if (p < CAND_CAP) s_list[tokB * CAND_CAP + p] = i2B; }
    if (b3B >= thrB) { int p = atomicAdd(&s_cnt[tokB], 1); if (p < CAND_CAP) s_list[tokB * CAND_CAP + p] = i3B; }
    if (b4B >= thrB) { int p = atomicAdd(&s_cnt[tokB], 1); if (p < CAND_CAP) s_list[tokB * CAND_CAP + p] = i4B; }
    __syncthreads();

    // ---- stage B: fp32 rescore + outputs + loss (validated path) ----
    float lsum = 0.0f;
    if (tid < MCTA) {
        const int t = tok0 + tid;
        float zn[E_DIM];
        const float4* zr = (const float4*)(z + (size_t)t * E_DIM);
        float ss = 0.0f;
        #pragma unroll
        for (int j = 0; j < 8; j++) {
            float4 v = zr[j];
            zn[4*j+0] = v.x; zn[4*j+1] = v.y; zn[4*j+2] = v.z; zn[4*j+3] = v.w;
            ss += v.x*v.x + v.y*v.y + v.z*v.z + v.w*v.w;
        }
        float inv = 1.0f / fmaxf(sqrtf(ss), 1e-12f);
        #pragma unroll
        for (int d = 0; d < E_DIM; d++) zn[d] *= inv;

        int nc = s_cnt[tid]; if (nc > CAND_CAP) nc = CAND_CAP;
        float best = -3.4e38f;
        int   bi   = 0x7FFFFFFF;
        for (int j = 0; j < nc; j++) {
            int ci = s_list[tid * CAND_CAP + j];
            const float* er = g_en + (size_t)ci * E_DIM;
            float dot = 0.0f;
            #pragma unroll
            for (int d = 0; d < E_DIM; d++) dot = fmaf(zn[d], er[d], dot);
            float s = dot + g_bias[ci];
            if (s > best || (s == best && ci < bi)) { best = s; bi = ci; }
        }

        float o[E_DIM];
        const float* eq = g_en + (size_t)bi * E_DIM;
        #pragma unroll
        for (int d = 0; d < E_DIM; d++) {
            float df = eq[d] - zn[d];
            lsum += df * df;
            o[d] = zn[d] + df;
        }
        float4* orow = (float4*)(out + (size_t)t * E_DIM);
        #pragma unroll
        for (int j = 0; j < 8; j++)
            orow[j] = make_float4(o[4*j], o[4*j+1], o[4*j+2], o[4*j+3]);
        out[(size_t)T_TOK * E_DIM + 1 + t] = (float)bi;
    }

    __syncthreads();
    float* s_red = (float*)smem;
    s_red[tid] = lsum;
    __syncthreads();
    #pragma unroll
    for (int k = 64; k; k >>= 1) {
        if (tid < k) s_red[tid] += s_red[tid + k];
        __syncthreads();
    }
    if (tid == 0) g_part[blockIdx.x] = s_red[0];
}

// =====================================================================
// Final loss: 1.25 * sum / (T*D) over 512 partials
// =====================================================================
__global__ void finish_kernel(float* __restrict__ out) {
    __shared__ float s[256];
    int tid = threadIdx.x;
    s[tid] = g_part[tid] + g_part[tid + 256];
    __syncthreads();
    #pragma unroll
    for (int k = 128; k; k >>= 1) {
        if (tid < k) s[tid] += s[tid + k];
        __syncthreads();
    }
    if (tid == 0) out[(size_t)T_TOK * E_DIM] = 1.25f * s[0] / (float)(T_TOK * E_DIM);
}

extern "C" void kernel_launch(void* const* d_in, const int* in_sizes, int n_in,
                              void* d_out, int out_size) {
    const float* z   = (const float*)d_in[0];
    const float* emb = (const float*)d_in[1];
    float* out = (float*)d_out;

    cudaFuncSetAttribute(vq_main_kernel, cudaFuncAttributeMaxDynamicSharedMemorySize, SMEM_TOTAL);

    prep_kernel<<<N_E / 8, 256>>>(emb);
    vq_main_kernel<<<GRID_MAIN, 128, SMEM_TOTAL>>>(z, out);
    finish_kernel<<<1, 256>>>(out);
}